// round 12
// baseline (speedup 1.0000x reference)
#include <cuda_runtime.h>
#include <math.h>

// DGPLoss fused single-kernel: band blocks + cp.async pipeline, 4 ch/stage.
//   seg_feat: [4, 64, 512, 512] fp32   (d_in[0])
//   dep_true: [4, 1, 512, 512]  fp32   (d_in[1])
//   out[0]  : scalar fp32
//
// Block = one 5-row patch band x batch (408 blocks, 640 thr, 3 blocks/SM).
// Stage = 4 channels (20KB), double-buffered (40KB static smem). 16 loop
// iterations: wait_group 0 (my stage-i copies done; nothing younger is
// committed yet) -> __syncthreads (everyone's stage-i data visible; buf
// (i+1)&1's prior readers all passed) -> issue 4 cp.asyncs for stage i+1 ->
// compute 4 channels (quad LDS.128 + 2 center scalars per channel, centers
// come from row-2 threads' copies in the same tile). Barriers: 16 total
// (was 64). Ticket-elected last block reduces 408 partials.

#define EPSF 1e-8f
#define EPS2 1e-16f
#define CS   262144              // 512*512
#define NBANDS 102
#define NBAT 4
#define NPART (NBANDS * NBAT)    // 408
#define CHPS 4                   // channels per stage
#define NITER 16                 // 64 / CHPS
#define CH_BYTES (5 * 512 * 4)   // 10240 per channel

typedef unsigned int u32;

__device__ float2 g_part[NPART];
__device__ u32    g_ticket;   // zero-init; reset by last block each run

__device__ __forceinline__ u32 smem_u32(const void* p) {
    return (u32)__cvta_generic_to_shared(p);
}
__device__ __forceinline__ void cp_async16(u32 dst, const float* src) {
    asm volatile("cp.async.cg.shared.global [%0], [%1], 16;\n"
                 :: "r"(dst), "l"(src) : "memory");
}
__device__ __forceinline__ void cp_commit() {
    asm volatile("cp.async.commit_group;\n" ::: "memory");
}
__device__ __forceinline__ void cp_wait0() {
    asm volatile("cp.async.wait_group 0;\n" ::: "memory");
}

__global__ __launch_bounds__(640, 3)
void dgp_fused(const float* __restrict__ seg, const float* __restrict__ dep,
               float* __restrict__ out)
{
    __shared__ float  sbuf[2][CHPS][5][512];   // 40 KB
    __shared__ float2 s_red[20];
    __shared__ bool   isLast;

    const int tid = threadIdx.x;
    const int r   = tid >> 7;        // row within band: 0..4
    const int wl  = tid & 127;
    const int w0  = wl << 2;         // 0..508
    const int j   = blockIdx.x;      // band 0..101
    const int b   = blockIdx.y;      // batch 0..3
    const int h   = j * 5 + r;
    const int hc  = j * 5 + 2;

    const int pA  = w0 / 5;
    const int pB  = (w0 + 3) / 5;    // may be 102 -> wcB=512 spills to next row slot (finite, masked)
    const int wcA = pA * 5 + 2;
    const int wcB = pB * 5 + 2;
    const bool sB1 = ((w0 + 1) / 5) != pA;
    const bool sB2 = ((w0 + 2) / 5) != pA;
    const bool sB3 = (pB != pA);

    const int segBase = b * (64 * CS);   // fits int32
    const float* __restrict__ src0 = seg + segBase + h * 512 + w0;

    const u32 sb     = smem_u32(sbuf);
    const u32 dstoff = (u32)((r * 512 + w0) * 4);

    // prologue: stage 0 (channels 0..3) in flight, one commit group
    #pragma unroll
    for (int k = 0; k < CHPS; ++k)
        cp_async16(sb + k * CH_BYTES + dstoff, src0 + k * CS);
    cp_commit();

    float a0 = 0.f, a1 = 0.f, a2 = 0.f, a3 = 0.f;

    #pragma unroll 2
    for (int i = 0; i < NITER; ++i) {
        cp_wait0();          // my stage-i copies arrived (nothing younger committed)
        __syncthreads();     // all threads' stage-i data visible; buf (i+1)&1 reusable

        // issue stage i+1 (4 channels, one group) into the other buffer
        if (i + 1 < NITER) {
            const u32 base = sb + (u32)(((i + 1) & 1) * CHPS) * CH_BYTES + dstoff;
            const float* s = src0 + (i + 1) * (CHPS * CS);
            #pragma unroll
            for (int k = 0; k < CHPS; ++k)
                cp_async16(base + k * CH_BYTES, s + k * CS);
        }
        cp_commit();

        // compute 4 channels from stage i
        const int st = i & 1;
        #pragma unroll
        for (int k = 0; k < CHPS; ++k) {
            const float4 p  = *(const float4*)&sbuf[st][k][r][w0];
            const float  qA = sbuf[st][k][2][wcA];
            const float  qB = sbuf[st][k][2][wcB];
            const float  q1 = sB1 ? qB : qA;
            const float  q2 = sB2 ? qB : qA;
            const float  q3 = sB3 ? qB : qA;
            float d;
            d = qA - p.x; a0 = fmaf(d, d, a0);
            d = q1 - p.y; a1 = fmaf(d, d, a1);
            d = q2 - p.z; a2 = fmaf(d, d, a2);
            d = q3 - p.w; a3 = fmaf(d, d, a3);
        }
    }

    // ---- depth branch + mask (direct global; tiny) ----
    const int depBase = b * CS;
    const float4 dq  = *(const float4*)(dep + depBase + h * 512 + w0);
    const float  dcA = dep[depBase + hc * 512 + wcA];
    const float  dcB = dep[depBase + hc * 512 + wcB];

    const float dcv[4] = { dcA, sB1 ? dcB : dcA, sB2 ? dcB : dcA, sB3 ? dcB : dcA };
    const int   wcv[4] = { wcA, sB1 ? wcB : wcA, sB2 ? wcB : wcA, sB3 ? wcB : wcA };
    const float av [4] = { a0, a1, a2, a3 };
    const float dpv[4] = { dq.x, dq.y, dq.z, dq.w };

    float sum = 0.f, cnt = 0.f;
    #pragma unroll
    for (int k = 0; k < 4; ++k) {
        const float dd = fabsf(dcv[k] - dpv[k]);
        const bool ic  = (r == 2) && (w0 + k == wcv[k]);
        const bool m   = (dd > EPSF) && (av[k] > EPS2) && (dpv[k] > EPSF) &&
                         !ic && (w0 + k < 510);
        if (m) {
            sum += __expf(-fmaf(dd, 0.1f, av[k]));
            cnt += 1.f;
        }
    }

    // ---- block reduce (20 warps) ----
    #pragma unroll
    for (int o = 16; o > 0; o >>= 1) {
        sum += __shfl_down_sync(0xFFFFFFFFu, sum, o);
        cnt += __shfl_down_sync(0xFFFFFFFFu, cnt, o);
    }
    const int lane = tid & 31;
    const int wid  = tid >> 5;
    if (lane == 0) s_red[wid] = make_float2(sum, cnt);
    __syncthreads();

    if (wid == 0) {
        float s = (lane < 20) ? s_red[lane].x : 0.f;
        float c = (lane < 20) ? s_red[lane].y : 0.f;
        #pragma unroll
        for (int o = 16; o > 0; o >>= 1) {
            s += __shfl_down_sync(0xFFFFFFFFu, s, o);
            c += __shfl_down_sync(0xFFFFFFFFu, c, o);
        }
        if (lane == 0) {
            g_part[j + NBANDS * b] = make_float2(s, c);
            __threadfence();
            const u32 t = atomicAdd(&g_ticket, 1u);
            isLast = (t == NPART - 1);
        }
    }
    __syncthreads();

    // ---- final deterministic reduction by the last block ----
    if (isLast) {
        __threadfence();
        float s = 0.f, c = 0.f;
        if (tid < NPART) {               // 408 < 640: one partial per thread
            const float2 v = g_part[tid];
            s = v.x; c = v.y;
        }
        #pragma unroll
        for (int o = 16; o > 0; o >>= 1) {
            s += __shfl_down_sync(0xFFFFFFFFu, s, o);
            c += __shfl_down_sync(0xFFFFFFFFu, c, o);
        }
        __syncthreads();                 // s_red reuse
        if (lane == 0) s_red[wid] = make_float2(s, c);
        __syncthreads();
        if (wid == 0) {
            float ts = (lane < 20) ? s_red[lane].x : 0.f;
            float tc = (lane < 20) ? s_red[lane].y : 0.f;
            #pragma unroll
            for (int o = 16; o > 0; o >>= 1) {
                ts += __shfl_down_sync(0xFFFFFFFFu, ts, o);
                tc += __shfl_down_sync(0xFFFFFFFFu, tc, o);
            }
            if (lane == 0) {
                out[0] = ts / fmaxf(tc, 1.0f);
                g_ticket = 0u;           // reset for next graph replay
            }
        }
    }
}

extern "C" void kernel_launch(void* const* d_in, const int* in_sizes, int n_in,
                              void* d_out, int out_size) {
    const float* seg = (const float*)d_in[0];   // [4,64,512,512]
    const float* dep = (const float*)d_in[1];   // [4,1,512,512]
    float* out = (float*)d_out;

    dim3 grid(NBANDS, NBAT);
    dgp_fused<<<grid, 640>>>(seg, dep, out);
}

// round 13
// speedup vs baseline: 1.1190x; 1.1190x over previous
#include <cuda_runtime.h>
#include <math.h>

// DGPLoss fused single-kernel: band blocks + cp.async pipeline, 2 ch/stage.
//   seg_feat: [4, 64, 512, 512] fp32   (d_in[0])
//   dep_true: [4, 1, 512, 512]  fp32   (d_in[1])
//   out[0]  : scalar fp32
//
// Block = one 5-row patch band x batch (408 blocks, 640 thr, 3 blocks/SM).
// Stage = 2 channels (20KB), double-buffered (40KB static smem -> same
// 3-blocks/SM occupancy as R11). 32 loop iterations: wait_group 0 ->
// __syncthreads -> issue 2 cp.asyncs for stage i+1 -> compute 2 channels
// (quad LDS.128 + 2 center scalars; centers come from row-2 threads' copies
// in the same tile). Barriers: 32 total (R11 had 64) -> half the fixed
// per-channel pipeline tax. Ticket-elected last block reduces 408 partials.

#define EPSF 1e-8f
#define EPS2 1e-16f
#define CS   262144              // 512*512
#define NBANDS 102
#define NBAT 4
#define NPART (NBANDS * NBAT)    // 408
#define CHPS 2                   // channels per stage
#define NITER 32                 // 64 / CHPS
#define CH_BYTES (5 * 512 * 4)   // 10240 per channel

typedef unsigned int u32;

__device__ float2 g_part[NPART];
__device__ u32    g_ticket;   // zero-init; reset by last block each run

__device__ __forceinline__ u32 smem_u32(const void* p) {
    return (u32)__cvta_generic_to_shared(p);
}
__device__ __forceinline__ void cp_async16(u32 dst, const float* src) {
    asm volatile("cp.async.cg.shared.global [%0], [%1], 16;\n"
                 :: "r"(dst), "l"(src) : "memory");
}
__device__ __forceinline__ void cp_commit() {
    asm volatile("cp.async.commit_group;\n" ::: "memory");
}
__device__ __forceinline__ void cp_wait0() {
    asm volatile("cp.async.wait_group 0;\n" ::: "memory");
}

__global__ __launch_bounds__(640, 3)
void dgp_fused(const float* __restrict__ seg, const float* __restrict__ dep,
               float* __restrict__ out)
{
    __shared__ float  sbuf[2][CHPS][5][512];   // 2*2*5*512*4 = 40 KB
    __shared__ float2 s_red[20];
    __shared__ bool   isLast;

    const int tid = threadIdx.x;
    const int r   = tid >> 7;        // row within band: 0..4
    const int wl  = tid & 127;
    const int w0  = wl << 2;         // 0..508
    const int j   = blockIdx.x;      // band 0..101
    const int b   = blockIdx.y;      // batch 0..3
    const int h   = j * 5 + r;
    const int hc  = j * 5 + 2;

    const int pA  = w0 / 5;
    const int pB  = (w0 + 3) / 5;    // may be 102 -> wcB=512 spills into next row slot (finite, masked)
    const int wcA = pA * 5 + 2;
    const int wcB = pB * 5 + 2;
    const bool sB1 = ((w0 + 1) / 5) != pA;
    const bool sB2 = ((w0 + 2) / 5) != pA;
    const bool sB3 = (pB != pA);

    const int segBase = b * (64 * CS);   // fits int32
    const float* __restrict__ src0 = seg + segBase + h * 512 + w0;

    const u32 sb     = smem_u32(sbuf);
    const u32 dstoff = (u32)((r * 512 + w0) * 4);

    // prologue: stage 0 (channels 0..1) in flight, one commit group
    #pragma unroll
    for (int k = 0; k < CHPS; ++k)
        cp_async16(sb + k * CH_BYTES + dstoff, src0 + k * CS);
    cp_commit();

    float a0 = 0.f, a1 = 0.f, a2 = 0.f, a3 = 0.f;

    #pragma unroll 4
    for (int i = 0; i < NITER; ++i) {
        cp_wait0();          // my stage-i copies arrived (nothing younger committed)
        __syncthreads();     // all threads' stage-i data visible; other buf reusable

        // issue stage i+1 (2 channels, one group) into the other buffer
        if (i + 1 < NITER) {
            const u32 base = sb + (u32)(((i + 1) & 1) * CHPS) * CH_BYTES + dstoff;
            const float* s = src0 + (i + 1) * (CHPS * CS);
            #pragma unroll
            for (int k = 0; k < CHPS; ++k)
                cp_async16(base + k * CH_BYTES, s + k * CS);
        }
        cp_commit();

        // compute 2 channels from stage i
        const int st = i & 1;
        #pragma unroll
        for (int k = 0; k < CHPS; ++k) {
            const float4 p  = *(const float4*)&sbuf[st][k][r][w0];
            const float  qA = sbuf[st][k][2][wcA];
            const float  qB = sbuf[st][k][2][wcB];
            const float  q1 = sB1 ? qB : qA;
            const float  q2 = sB2 ? qB : qA;
            const float  q3 = sB3 ? qB : qA;
            float d;
            d = qA - p.x; a0 = fmaf(d, d, a0);
            d = q1 - p.y; a1 = fmaf(d, d, a1);
            d = q2 - p.z; a2 = fmaf(d, d, a2);
            d = q3 - p.w; a3 = fmaf(d, d, a3);
        }
    }

    // ---- depth branch + mask (direct global; tiny) ----
    const int depBase = b * CS;
    const float4 dq  = *(const float4*)(dep + depBase + h * 512 + w0);
    const float  dcA = dep[depBase + hc * 512 + wcA];
    const float  dcB = dep[depBase + hc * 512 + wcB];

    const float dcv[4] = { dcA, sB1 ? dcB : dcA, sB2 ? dcB : dcA, sB3 ? dcB : dcA };
    const int   wcv[4] = { wcA, sB1 ? wcB : wcA, sB2 ? wcB : wcA, sB3 ? wcB : wcA };
    const float av [4] = { a0, a1, a2, a3 };
    const float dpv[4] = { dq.x, dq.y, dq.z, dq.w };

    float sum = 0.f, cnt = 0.f;
    #pragma unroll
    for (int k = 0; k < 4; ++k) {
        const float dd = fabsf(dcv[k] - dpv[k]);
        const bool ic  = (r == 2) && (w0 + k == wcv[k]);
        const bool m   = (dd > EPSF) && (av[k] > EPS2) && (dpv[k] > EPSF) &&
                         !ic && (w0 + k < 510);
        if (m) {
            sum += __expf(-fmaf(dd, 0.1f, av[k]));
            cnt += 1.f;
        }
    }

    // ---- block reduce (20 warps) ----
    #pragma unroll
    for (int o = 16; o > 0; o >>= 1) {
        sum += __shfl_down_sync(0xFFFFFFFFu, sum, o);
        cnt += __shfl_down_sync(0xFFFFFFFFu, cnt, o);
    }
    const int lane = tid & 31;
    const int wid  = tid >> 5;
    if (lane == 0) s_red[wid] = make_float2(sum, cnt);
    __syncthreads();

    if (wid == 0) {
        float s = (lane < 20) ? s_red[lane].x : 0.f;
        float c = (lane < 20) ? s_red[lane].y : 0.f;
        #pragma unroll
        for (int o = 16; o > 0; o >>= 1) {
            s += __shfl_down_sync(0xFFFFFFFFu, s, o);
            c += __shfl_down_sync(0xFFFFFFFFu, c, o);
        }
        if (lane == 0) {
            g_part[j + NBANDS * b] = make_float2(s, c);
            __threadfence();
            const u32 t = atomicAdd(&g_ticket, 1u);
            isLast = (t == NPART - 1);
        }
    }
    __syncthreads();

    // ---- final deterministic reduction by the last block ----
    if (isLast) {
        __threadfence();
        float s = 0.f, c = 0.f;
        if (tid < NPART) {               // 408 < 640: one partial per thread
            const float2 v = g_part[tid];
            s = v.x; c = v.y;
        }
        #pragma unroll
        for (int o = 16; o > 0; o >>= 1) {
            s += __shfl_down_sync(0xFFFFFFFFu, s, o);
            c += __shfl_down_sync(0xFFFFFFFFu, c, o);
        }
        __syncthreads();                 // s_red reuse
        if (lane == 0) s_red[wid] = make_float2(s, c);
        __syncthreads();
        if (wid == 0) {
            float ts = (lane < 20) ? s_red[lane].x : 0.f;
            float tc = (lane < 20) ? s_red[lane].y : 0.f;
            #pragma unroll
            for (int o = 16; o > 0; o >>= 1) {
                ts += __shfl_down_sync(0xFFFFFFFFu, ts, o);
                tc += __shfl_down_sync(0xFFFFFFFFu, tc, o);
            }
            if (lane == 0) {
                out[0] = ts / fmaxf(tc, 1.0f);
                g_ticket = 0u;           // reset for next graph replay
            }
        }
    }
}

extern "C" void kernel_launch(void* const* d_in, const int* in_sizes, int n_in,
                              void* d_out, int out_size) {
    const float* seg = (const float*)d_in[0];   // [4,64,512,512]
    const float* dep = (const float*)d_in[1];   // [4,1,512,512]
    float* out = (float*)d_out;

    dim3 grid(NBANDS, NBAT);
    dgp_fused<<<grid, 640>>>(seg, dep, out);
}